// round 7
// baseline (speedup 1.0000x reference)
#include <cuda_runtime.h>
#include <math.h>
#include <stdint.h>

// Problem constants
#define Bv   32
#define Sv   512
#define Dv   768
#define Mv   32
#define Tv   30
#define Hv   12
#define HDv  64
#define DFFv 3072
#define Lv   4
#define Ev   100000
#define NT   1024           // B*M token rows

// ---------------- scratch (static device memory; no allocations) -------------
__device__ float g_x[NT * Dv];          // residual stream
__device__ float g_qkv[NT * 3 * Dv];    // [1024,2304]
__device__ float g_buf1[NT * DFFv];     // attn-out / FF hidden
__device__ float g_hid[NT * 100];       // classifier hidden
__device__ float g_part[6 * NT * Dv];   // split-K partials

// ======================= helpers ============================================
__device__ __forceinline__ uint32_t f2tf32(float f) {
    uint32_t u;
    asm("cvt.rna.tf32.f32 %0, %1;" : "=r"(u) : "f"(f));
    return u;
}

__device__ __forceinline__ void mma_tf32(float* c, const uint32_t* a, const uint32_t* b) {
    asm volatile(
        "mma.sync.aligned.m16n8k8.row.col.f32.tf32.tf32.f32 "
        "{%0,%1,%2,%3}, {%4,%5,%6,%7}, {%8,%9}, {%0,%1,%2,%3};"
        : "+f"(c[0]), "+f"(c[1]), "+f"(c[2]), "+f"(c[3])
        : "r"(a[0]), "r"(a[1]), "r"(a[2]), "r"(a[3]),
          "r"(b[0]), "r"(b[1]));
}

// ======================= TF32 tensor-core GEMM v4 ===========================
// C = A @ W^T (+bias,+relu). A:[1024,K] f32 row-major, W:[N,K] f32 row-major.
// Tile 128x128x32, 256 threads, 8 warps (2x4), warp tile 64x32.
// Producer: LDG.128 -> cvt.rna.tf32 -> STS.128 (tf32 bits live in smem).
// Consumer: scalar LDS only (R3-proven conflict-free mapping), no cvt.
// Double-buffered via register staging; one __syncthreads per ktile.
#define SMS 4608   // words per tile stage: 128*36

__global__ void __launch_bounds__(256) gemm_tc(
    const float* __restrict__ A, const float* __restrict__ W,
    const float* __restrict__ bias, float* __restrict__ C,
    int N, int K, int kChunk, int relu)
{
    extern __shared__ uint32_t smbuf[];
    uint32_t* AsBase = smbuf;              // [2][128][36]
    uint32_t* WsBase = smbuf + 2 * SMS;    // [2][128][36]

    const int tid = threadIdx.x;
    const int lane = tid & 31, wid = tid >> 5;
    const int wy = wid >> 2, wx = wid & 3;      // 2 x 4 warps
    const int lm = lane >> 2, lk = lane & 3;
    const int rowBase = blockIdx.y * 128;
    const int colBase = blockIdx.x * 128;
    const int kBase = blockIdx.z * kChunk;
    const int kEnd = min(K, kBase + kChunk);
    const int nT = (kEnd - kBase + 31) >> 5;

    float* Cp = C;
    if (gridDim.z > 1) Cp += (size_t)blockIdx.z * ((size_t)NT * N);

    float acc[4][4][4];
    #pragma unroll
    for (int i = 0; i < 4; i++)
        #pragma unroll
        for (int j = 0; j < 4; j++)
            #pragma unroll
            for (int q = 0; q < 4; q++) acc[i][j][q] = 0.f;

    // per-thread staging: 4 float4 of A + 4 float4 of W per ktile
    float4 ra[4], rb[4];
    const int sr = tid >> 3;         // 0..31 : base row index stride 32
    const int sk = (tid & 7) * 4;    // k-word offset 0,4,..28

    #define LOAD_TILE(kt)                                                       \
    {                                                                           \
        int gk = kBase + (kt) * 32 + sk;                                        \
        bool okk = (gk + 4 <= kEnd);                                            \
        _Pragma("unroll")                                                       \
        for (int i = 0; i < 4; i++) {                                           \
            int r = sr + i * 32;                                                \
            const float* pa = A + (size_t)(rowBase + r) * K + gk;               \
            ra[i] = okk ? *(const float4*)pa : make_float4(0.f, 0.f, 0.f, 0.f); \
            int n = colBase + r;                                                \
            const float* pb = W + (size_t)n * K + gk;                           \
            rb[i] = (okk && n < N) ? *(const float4*)pb                         \
                                   : make_float4(0.f, 0.f, 0.f, 0.f);           \
        }                                                                       \
    }

    #define STORE_TILE(buf)                                                     \
    {                                                                           \
        uint32_t* as = AsBase + (buf) * SMS;                                    \
        uint32_t* ws = WsBase + (buf) * SMS;                                    \
        _Pragma("unroll")                                                       \
        for (int i = 0; i < 4; i++) {                                           \
            int r = sr + i * 32;                                                \
            uint4 av = make_uint4(f2tf32(ra[i].x), f2tf32(ra[i].y),             \
                                  f2tf32(ra[i].z), f2tf32(ra[i].w));            \
            uint4 wv = make_uint4(f2tf32(rb[i].x), f2tf32(rb[i].y),             \
                                  f2tf32(rb[i].z), f2tf32(rb[i].w));            \
            *(uint4*)(as + r * 36 + sk) = av;                                   \
            *(uint4*)(ws + r * 36 + sk) = wv;                                   \
        }                                                                       \
    }

    LOAD_TILE(0);
    STORE_TILE(0);
    __syncthreads();

    for (int t = 0; t < nT; t++) {
        const int cur = t & 1;
        if (t + 1 < nT) LOAD_TILE(t + 1);

        const uint32_t* as = AsBase + cur * SMS;
        const uint32_t* ws = WsBase + cur * SMS;
        #pragma unroll
        for (int k8 = 0; k8 < 4; k8++) {
            const int kb = k8 * 8;
            uint32_t af[4][4], bf[4][2];
            #pragma unroll
            for (int mt = 0; mt < 4; mt++) {
                int m = wy * 64 + mt * 16 + lm;
                af[mt][0] = as[m * 36 + kb + lk];
                af[mt][1] = as[(m + 8) * 36 + kb + lk];
                af[mt][2] = as[m * 36 + kb + 4 + lk];
                af[mt][3] = as[(m + 8) * 36 + kb + 4 + lk];
            }
            #pragma unroll
            for (int nt = 0; nt < 4; nt++) {
                int n = wx * 32 + nt * 8 + lm;
                bf[nt][0] = ws[n * 36 + kb + lk];
                bf[nt][1] = ws[n * 36 + kb + 4 + lk];
            }
            #pragma unroll
            for (int mt = 0; mt < 4; mt++)
                #pragma unroll
                for (int nt = 0; nt < 4; nt++)
                    mma_tf32(acc[mt][nt], af[mt], bf[nt]);
        }

        if (t + 1 < nT) STORE_TILE(cur ^ 1);
        __syncthreads();
    }

    // epilogue
    #pragma unroll
    for (int mt = 0; mt < 4; mt++) {
        #pragma unroll
        for (int nt = 0; nt < 4; nt++) {
            int r0 = rowBase + wy * 64 + mt * 16 + lm;
            int c0 = colBase + wx * 32 + nt * 8 + lk * 2;
            float bx = 0.f, by = 0.f;
            if (bias) {
                if (c0 < N)     bx = bias[c0];
                if (c0 + 1 < N) by = bias[c0 + 1];
            }
            float v00 = acc[mt][nt][0] + bx, v01 = acc[mt][nt][1] + by;
            float v10 = acc[mt][nt][2] + bx, v11 = acc[mt][nt][3] + by;
            if (relu) {
                v00 = fmaxf(v00, 0.f); v01 = fmaxf(v01, 0.f);
                v10 = fmaxf(v10, 0.f); v11 = fmaxf(v11, 0.f);
            }
            if (c0 + 1 < N) {
                *(float2*)&Cp[(size_t)r0 * N + c0]       = make_float2(v00, v01);
                *(float2*)&Cp[(size_t)(r0 + 8) * N + c0] = make_float2(v10, v11);
            } else if (c0 < N) {
                Cp[(size_t)r0 * N + c0]       = v00;
                Cp[(size_t)(r0 + 8) * N + c0] = v10;
            }
        }
    }
}
#define GEMM_SMEM (4 * SMS * (int)sizeof(uint32_t))   // 73728 bytes

// ======================= mention pooling ====================================
__global__ void __launch_bounds__(128) pool_kernel(
    const float* __restrict__ lhs, const float* __restrict__ attn_w,
    const float* __restrict__ attn_b_p, const int* __restrict__ pos,
    const int* __restrict__ emask, float* __restrict__ x)
{
    int bm = blockIdx.x;
    int b = bm / Mv;
    __shared__ float logit[Tv];
    __shared__ float score[Tv];
    __shared__ int   validv[Tv];

    int tid = threadIdx.x, lane = tid & 31, warp = tid >> 5;

    if (tid == 0) {
        int ok = (emask[bm] != 0);
        int alive = 1;
        for (int t = 0; t < Tv; t++) {
            if (pos[bm * Tv + t] == -1) alive = 0;
            validv[t] = ok & alive;
        }
    }
    __syncthreads();

    float ab = attn_b_p[0];
    const float* lb = lhs + (size_t)b * Sv * Dv;

    for (int t = warp; t < Tv; t += 4) {
        float s = 0.f;
        for (int d = lane; d < Dv; d += 32) s += lb[t * Dv + d] * attn_w[d];
        for (int o = 16; o; o >>= 1) s += __shfl_xor_sync(0xffffffffu, s, o);
        if (lane == 0) logit[t] = (validv[t] ? s : 0.f) + ab;
    }
    __syncthreads();

    if (tid < 32) {
        float v = (tid < Tv) ? logit[tid] : -INFINITY;
        float mx = v;
        for (int o = 16; o; o >>= 1) mx = fmaxf(mx, __shfl_xor_sync(0xffffffffu, mx, o));
        float e = (tid < Tv) ? expf(v - mx) : 0.f;
        float sm = e;
        for (int o = 16; o; o >>= 1) sm += __shfl_xor_sync(0xffffffffu, sm, o);
        if (tid < Tv) score[tid] = e / sm;
    }
    __syncthreads();

    for (int d = tid; d < Dv; d += 128) {
        float s = 0.f;
        #pragma unroll
        for (int t = 0; t < Tv; t++)
            if (validv[t]) s += score[t] * lb[t * Dv + d];
        x[(size_t)bm * Dv + d] = s;
    }
}

// ======= attention: 16 query rows per block, 128 threads, grid 768 ==========
__global__ void __launch_bounds__(128) attn_kernel(
    const float* __restrict__ qkv, float* __restrict__ o)
{
    const int bh = blockIdx.x >> 1;
    const int half = blockIdx.x & 1;
    const int b = bh / Hv, h = bh % Hv;
    const int r0 = half * 16;

    __shared__ float q[16][68];
    __shared__ float kk[32][68];
    __shared__ float vv[32][68];
    __shared__ float a[16][33];

    const int tid = threadIdx.x;
    const float* base = qkv + (size_t)(b * Mv) * (3 * Dv) + h * HDv;

    #pragma unroll
    for (int rep = 0; rep < 8; rep++) {
        int idx = tid + rep * 128;
        int i = idx >> 6, d = idx & 63;
        q[i][d] = base[(size_t)(r0 + i) * (3 * Dv) + d];
    }
    #pragma unroll
    for (int rep = 0; rep < 16; rep++) {
        int idx = tid + rep * 128;
        int i = idx >> 6, d = idx & 63;
        const float* row = base + (size_t)i * (3 * Dv) + d;
        kk[i][d] = row[Dv];
        vv[i][d] = row[2 * Dv];
    }
    __syncthreads();

    #pragma unroll
    for (int rep = 0; rep < 4; rep++) {
        int idx = tid + rep * 128;
        int i = idx >> 5, j = idx & 31;
        float s = 0.f;
        #pragma unroll
        for (int d = 0; d < 64; d += 4) {
            float4 qa = *(const float4*)&q[i][d];
            float4 ka = *(const float4*)&kk[j][d];
            s += qa.x * ka.x + qa.y * ka.y + qa.z * ka.z + qa.w * ka.w;
        }
        a[i][j] = s * 0.125f;
    }
    __syncthreads();

    int warp = tid >> 5, lane = tid & 31;
    #pragma unroll
    for (int r = 0; r < 4; r++) {
        int i = warp * 4 + r;
        float v = a[i][lane];
        float mx = v;
        for (int off = 16; off; off >>= 1) mx = fmaxf(mx, __shfl_xor_sync(0xffffffffu, mx, off));
        float e = expf(v - mx);
        float sm = e;
        for (int off = 16; off; off >>= 1) sm += __shfl_xor_sync(0xffffffffu, sm, off);
        a[i][lane] = e / sm;
    }
    __syncthreads();

    float* obase = o + (size_t)(b * Mv + r0) * Dv + h * HDv;
    #pragma unroll
    for (int rep = 0; rep < 8; rep++) {
        int idx = tid + rep * 128;
        int i = idx >> 6, d = idx & 63;
        float s = 0.f;
        #pragma unroll
        for (int j = 0; j < 32; j++) s += a[i][j] * vv[j][d];
        obase[(size_t)i * Dv + d] = s;
    }
}

// ================ reduce split-K partials + bias, elementwise (cls1) ========
__global__ void __launch_bounds__(256) reduce_bias_kernel(
    float* __restrict__ dst, const float* __restrict__ part, int nPart,
    const float* __restrict__ bias, int Ncols, int relu)
{
    const size_t total = (size_t)NT * Ncols;
    const size_t stride = (size_t)gridDim.x * blockDim.x;
    for (size_t idx = (size_t)blockIdx.x * blockDim.x + threadIdx.x;
         idx < total; idx += stride) {
        float s = 0.f;
        for (int p = 0; p < nPart; p++) s += part[(size_t)p * total + idx];
        if (bias) s += bias[idx % Ncols];
        if (relu) s = fmaxf(s, 0.f);
        dst[idx] = s;
    }
}

// ======== reduce split-K partials + bias + residual add + LayerNorm =========
__global__ void __launch_bounds__(256) reduce_addln_kernel(
    float* __restrict__ x, const float* __restrict__ part, int nPart,
    const float* __restrict__ bias,
    const float* __restrict__ w, const float* __restrict__ b)
{
    __shared__ float sh[8];
    __shared__ float s_mean, s_inv;
    const int row = blockIdx.x;
    float* xr = x + (size_t)row * Dv;
    const int tid = threadIdx.x, lane = tid & 31, warp = tid >> 5;
    const size_t planeStride = (size_t)NT * Dv;

    float v[3];
    float sum = 0.f;
    #pragma unroll
    for (int i = 0; i < 3; i++) {
        int idx = tid + 256 * i;
        float d = bias[idx];
        for (int p = 0; p < nPart; p++)
            d += part[(size_t)p * planeStride + (size_t)row * Dv + idx];
        v[i] = xr[idx] + d;
        sum += v[i];
    }
    for (int o = 16; o; o >>= 1) sum += __shfl_xor_sync(0xffffffffu, sum, o);
    if (lane == 0) sh[warp] = sum;
    __syncthreads();
    if (tid == 0) {
        float s = 0.f;
        for (int i = 0; i < 8; i++) s += sh[i];
        s_mean = s * (1.f / (float)Dv);
    }
    __syncthreads();
    float mean = s_mean;

    float sq = 0.f;
    #pragma unroll
    for (int i = 0; i < 3; i++) { float c = v[i] - mean; sq += c * c; }
    for (int o = 16; o; o >>= 1) sq += __shfl_xor_sync(0xffffffffu, sq, o);
    if (lane == 0) sh[warp] = sq;
    __syncthreads();
    if (tid == 0) {
        float s = 0.f;
        for (int i = 0; i < 8; i++) s += sh[i];
        s_inv = rsqrtf(s * (1.f / (float)Dv) + 1e-5f);
    }
    __syncthreads();
    float inv = s_inv;

    #pragma unroll
    for (int i = 0; i < 3; i++) {
        int idx = tid + 256 * i;
        xr[idx] = (v[i] - mean) * inv * w[idx] + b[idx];
    }
}

// ======================= launcher ===========================================
extern "C" void kernel_launch(void* const* d_in, const int* in_sizes, int n_in,
                              void* d_out, int out_size)
{
    const float* lhs       = (const float*)d_in[0];
    const float* attn_w    = (const float*)d_in[1];
    const float* attn_b    = (const float*)d_in[2];
    const float* in_proj_w = (const float*)d_in[3];
    const float* in_proj_b = (const float*)d_in[4];
    const float* out_w     = (const float*)d_in[5];
    const float* out_b     = (const float*)d_in[6];
    const float* ln1_w     = (const float*)d_in[7];
    const float* ln1_b     = (const float*)d_in[8];
    const float* lin1_w    = (const float*)d_in[9];
    const float* lin1_b    = (const float*)d_in[10];
    const float* lin2_w    = (const float*)d_in[11];
    const float* lin2_b    = (const float*)d_in[12];
    const float* ln2_w     = (const float*)d_in[13];
    const float* ln2_b     = (const float*)d_in[14];
    const float* cls_w1    = (const float*)d_in[15];
    const float* cls_w2    = (const float*)d_in[16];
    const float* cls_b2    = (const float*)d_in[17];
    const int*   pos       = (const int*)d_in[18];
    const int*   emask     = (const int*)d_in[19];
    float* out = (float*)d_out;

    float *x, *qkv, *buf1, *hid, *part;
    cudaGetSymbolAddress((void**)&x,    g_x);
    cudaGetSymbolAddress((void**)&qkv,  g_qkv);
    cudaGetSymbolAddress((void**)&buf1, g_buf1);
    cudaGetSymbolAddress((void**)&hid,  g_hid);
    cudaGetSymbolAddress((void**)&part, g_part);

    cudaFuncSetAttribute(gemm_tc, cudaFuncAttributeMaxDynamicSharedMemorySize, GEMM_SMEM);

    pool_kernel<<<NT, 128>>>(lhs, attn_w, attn_b, pos, emask, x);

    for (int l = 0; l < Lv; l++) {
        // QKV: [1024,768]@[2304,768]^T, no split, bias fused -> 144 blocks
        gemm_tc<<<dim3(18, 8, 1), 256, GEMM_SMEM>>>(
            x, in_proj_w + (size_t)l * 3 * Dv * Dv, in_proj_b + (size_t)l * 3 * Dv,
            qkv, 3 * Dv, Dv, Dv, 0);
        // self-attention
        attn_kernel<<<Bv * Hv * 2, 128>>>(qkv, buf1);
        // out-proj: split-K 4 -> 192 blocks, reduce rides LN
        gemm_tc<<<dim3(6, 8, 4), 256, GEMM_SMEM>>>(
            buf1, out_w + (size_t)l * Dv * Dv, nullptr, part, Dv, Dv, 192, 0);
        reduce_addln_kernel<<<NT, 256>>>(x, part, 4, out_b + (size_t)l * Dv,
                                         ln1_w + (size_t)l * Dv, ln1_b + (size_t)l * Dv);
        // lin1: no split, bias+relu fused -> 192 blocks
        gemm_tc<<<dim3(24, 8, 1), 256, GEMM_SMEM>>>(
            x, lin1_w + (size_t)l * DFFv * Dv, lin1_b + (size_t)l * DFFv,
            buf1, DFFv, Dv, Dv, 1);
        // lin2: K=3072, split-K 6 -> 288 blocks, reduce rides LN
        gemm_tc<<<dim3(6, 8, 6), 256, GEMM_SMEM>>>(
            buf1, lin2_w + (size_t)l * Dv * DFFv, nullptr, part, Dv, DFFv, 512, 0);
        reduce_addln_kernel<<<NT, 256>>>(x, part, 6, lin2_b + (size_t)l * Dv,
                                         ln2_w + (size_t)l * Dv, ln2_b + (size_t)l * Dv);
    }

    // classifier stage 1: [1024,768]@[100,768]^T, split-K 4 -> 32 blocks
    gemm_tc<<<dim3(1, 8, 4), 256, GEMM_SMEM>>>(
        x, cls_w1, nullptr, part, 100, Dv, 192, 0);
    reduce_bias_kernel<<<1024, 256>>>(hid, part, 4, nullptr, 100, 0);
    // classifier stage 2: [1024,100]@[100000,100]^T -> 6256 blocks
    gemm_tc<<<dim3(782, 8, 1), 256, GEMM_SMEM>>>(
        hid, cls_w2, cls_b2, out, Ev, 100, 100, 0);
}

// round 8
// speedup vs baseline: 1.2505x; 1.2505x over previous
#include <cuda_runtime.h>
#include <math.h>
#include <stdint.h>

// Problem constants
#define Bv   32
#define Sv   512
#define Dv   768
#define Mv   32
#define Tv   30
#define Hv   12
#define HDv  64
#define DFFv 3072
#define Lv   4
#define Ev   100000
#define NT   1024           // B*M token rows

// ---------------- scratch (static device memory; no allocations) -------------
__device__ float g_x[NT * Dv];            // residual stream
__device__ float g_buf1[NT * DFFv];       // attn-out / FF hidden
__device__ float g_hid[NT * 100];         // classifier hidden
__device__ float g_part[2 * NT * DFFv];   // split-K partials (25MB, all uses fit)

// ======================= helpers ============================================
__device__ __forceinline__ uint32_t f2tf32(float f) {
    uint32_t u;
    asm("cvt.rna.tf32.f32 %0, %1;" : "=r"(u) : "f"(f));
    return u;
}

__device__ __forceinline__ void mma_tf32(float* c, const uint32_t* a, const uint32_t* b) {
    asm volatile(
        "mma.sync.aligned.m16n8k8.row.col.f32.tf32.tf32.f32 "
        "{%0,%1,%2,%3}, {%4,%5,%6,%7}, {%8,%9}, {%0,%1,%2,%3};"
        : "+f"(c[0]), "+f"(c[1]), "+f"(c[2]), "+f"(c[3])
        : "r"(a[0]), "r"(a[1]), "r"(a[2]), "r"(a[3]),
          "r"(b[0]), "r"(b[1]));
}

__device__ __forceinline__ void cp16(unsigned dst, const float* src, int bytes) {
    asm volatile("cp.async.ca.shared.global [%0], [%1], 16, %2;\n"
                 :: "r"(dst), "l"(src), "r"(bytes));
}

// ======================= TF32 tensor-core GEMM (R6-proven mainloop) =========
// C = A @ W^T (+bias,+relu). A:[1024,K] f32 row-major, W:[N,K] f32 row-major.
// Tile 128x128x32, 256 threads, 8 warps (2x4), warp tile 64x32.
// Double-buffered cp.async (fp32 in smem, cvt.rna at consume).
#define SMS 4608   // floats per tile stage: 128*36

__device__ __forceinline__ void fill_tiles(
    float* As, float* Ws, const float* __restrict__ A, const float* __restrict__ W,
    int rowBase, int colBase, int N, int K, int k0, int kEnd, int tid)
{
    #pragma unroll
    for (int i = 0; i < 4; i++) {
        int c = tid + i * 256;          // 0..1023
        int r = c >> 3, ck = c & 7;
        int gk = k0 + ck * 4;
        int ok = (gk < kEnd);
        const float* src = ok ? (A + (size_t)(rowBase + r) * K + gk) : A;
        unsigned d = (unsigned)__cvta_generic_to_shared(As + r * 36 + ck * 4);
        cp16(d, src, ok ? 16 : 0);
    }
    #pragma unroll
    for (int i = 0; i < 4; i++) {
        int c = tid + i * 256;
        int r = c >> 3, ck = c & 7;
        int gk = k0 + ck * 4;
        int n = colBase + r;
        int ok = (n < N) && (gk < kEnd);
        const float* src = ok ? (W + (size_t)n * K + gk) : W;
        unsigned d = (unsigned)__cvta_generic_to_shared(Ws + r * 36 + ck * 4);
        cp16(d, src, ok ? 16 : 0);
    }
}

__global__ void __launch_bounds__(256, 2) gemm_tc(
    const float* __restrict__ A, const float* __restrict__ W,
    const float* __restrict__ bias, float* __restrict__ C,
    int N, int K, int kChunk, int relu)
{
    extern __shared__ float smbuf[];
    float* AsBase = smbuf;              // [2][128][36]
    float* WsBase = smbuf + 2 * SMS;    // [2][128][36]

    const int tid = threadIdx.x;
    const int lane = tid & 31, wid = tid >> 5;
    const int wy = wid >> 2, wx = wid & 3;      // 2 x 4 warps
    const int lm = lane >> 2, lk = lane & 3;
    const int rowBase = blockIdx.y * 128;
    const int colBase = blockIdx.x * 128;
    const int kBase = blockIdx.z * kChunk;
    const int kEnd = min(K, kBase + kChunk);
    const int nT = (kEnd - kBase + 31) >> 5;

    float* Cp = C;
    if (gridDim.z > 1) Cp += (size_t)blockIdx.z * ((size_t)NT * N);

    float acc[4][4][4];
    #pragma unroll
    for (int i = 0; i < 4; i++)
        #pragma unroll
        for (int j = 0; j < 4; j++)
            #pragma unroll
            for (int q = 0; q < 4; q++) acc[i][j][q] = 0.f;

    fill_tiles(AsBase, WsBase, A, W, rowBase, colBase, N, K, kBase, kEnd, tid);
    asm volatile("cp.async.commit_group;\n" ::: "memory");

    for (int t = 0; t < nT; t++) {
        const int cur = t & 1;
        if (t + 1 < nT)
            fill_tiles(AsBase + (cur ^ 1) * SMS, WsBase + (cur ^ 1) * SMS,
                       A, W, rowBase, colBase, N, K, kBase + (t + 1) * 32, kEnd, tid);
        asm volatile("cp.async.commit_group;\n" ::: "memory");
        asm volatile("cp.async.wait_group 1;\n" ::: "memory");
        __syncthreads();

        const float* as = AsBase + cur * SMS;
        const float* ws = WsBase + cur * SMS;
        #pragma unroll
        for (int k8 = 0; k8 < 4; k8++) {
            const int kb = k8 * 8;
            uint32_t af[4][4], bf[4][2];
            #pragma unroll
            for (int mt = 0; mt < 4; mt++) {
                int m = wy * 64 + mt * 16 + lm;
                af[mt][0] = f2tf32(as[m * 36 + kb + lk]);
                af[mt][1] = f2tf32(as[(m + 8) * 36 + kb + lk]);
                af[mt][2] = f2tf32(as[m * 36 + kb + 4 + lk]);
                af[mt][3] = f2tf32(as[(m + 8) * 36 + kb + 4 + lk]);
            }
            #pragma unroll
            for (int nt = 0; nt < 4; nt++) {
                int n = wx * 32 + nt * 8 + lm;
                bf[nt][0] = f2tf32(ws[n * 36 + kb + lk]);
                bf[nt][1] = f2tf32(ws[n * 36 + kb + 4 + lk]);
            }
            #pragma unroll
            for (int mt = 0; mt < 4; mt++)
                #pragma unroll
                for (int nt = 0; nt < 4; nt++)
                    mma_tf32(acc[mt][nt], af[mt], bf[nt]);
        }
        __syncthreads();
    }

    // epilogue
    #pragma unroll
    for (int mt = 0; mt < 4; mt++) {
        #pragma unroll
        for (int nt = 0; nt < 4; nt++) {
            int r0 = rowBase + wy * 64 + mt * 16 + lm;
            int c0 = colBase + wx * 32 + nt * 8 + lk * 2;
            float bx = 0.f, by = 0.f;
            if (bias) {
                if (c0 < N)     bx = bias[c0];
                if (c0 + 1 < N) by = bias[c0 + 1];
            }
            float v00 = acc[mt][nt][0] + bx, v01 = acc[mt][nt][1] + by;
            float v10 = acc[mt][nt][2] + bx, v11 = acc[mt][nt][3] + by;
            if (relu) {
                v00 = fmaxf(v00, 0.f); v01 = fmaxf(v01, 0.f);
                v10 = fmaxf(v10, 0.f); v11 = fmaxf(v11, 0.f);
            }
            if (c0 + 1 < N) {
                *(float2*)&Cp[(size_t)r0 * N + c0]       = make_float2(v00, v01);
                *(float2*)&Cp[(size_t)(r0 + 8) * N + c0] = make_float2(v10, v11);
            } else if (c0 < N) {
                Cp[(size_t)r0 * N + c0]       = v00;
                Cp[(size_t)(r0 + 8) * N + c0] = v10;
            }
        }
    }
}
#define GEMM_SMEM (4 * SMS * (int)sizeof(float))   // 73728 bytes

// ======================= mention pooling ====================================
__global__ void __launch_bounds__(128) pool_kernel(
    const float* __restrict__ lhs, const float* __restrict__ attn_w,
    const float* __restrict__ attn_b_p, const int* __restrict__ pos,
    const int* __restrict__ emask, float* __restrict__ x)
{
    int bm = blockIdx.x;
    int b = bm / Mv;
    __shared__ float logit[Tv];
    __shared__ float score[Tv];
    __shared__ int   validv[Tv];

    int tid = threadIdx.x, lane = tid & 31, warp = tid >> 5;

    if (tid == 0) {
        int ok = (emask[bm] != 0);
        int alive = 1;
        for (int t = 0; t < Tv; t++) {
            if (pos[bm * Tv + t] == -1) alive = 0;
            validv[t] = ok & alive;
        }
    }
    __syncthreads();

    float ab = attn_b_p[0];
    const float* lb = lhs + (size_t)b * Sv * Dv;

    for (int t = warp; t < Tv; t += 4) {
        float s = 0.f;
        for (int d = lane; d < Dv; d += 32) s += lb[t * Dv + d] * attn_w[d];
        for (int o = 16; o; o >>= 1) s += __shfl_xor_sync(0xffffffffu, s, o);
        if (lane == 0) logit[t] = (validv[t] ? s : 0.f) + ab;
    }
    __syncthreads();

    if (tid < 32) {
        float v = (tid < Tv) ? logit[tid] : -INFINITY;
        float mx = v;
        for (int o = 16; o; o >>= 1) mx = fmaxf(mx, __shfl_xor_sync(0xffffffffu, mx, o));
        float e = (tid < Tv) ? expf(v - mx) : 0.f;
        float sm = e;
        for (int o = 16; o; o >>= 1) sm += __shfl_xor_sync(0xffffffffu, sm, o);
        if (tid < Tv) score[tid] = e / sm;
    }
    __syncthreads();

    for (int d = tid; d < Dv; d += 128) {
        float s = 0.f;
        #pragma unroll
        for (int t = 0; t < Tv; t++)
            if (validv[t]) s += score[t] * lb[t * Dv + d];
        x[(size_t)bm * Dv + d] = s;
    }
}

// ======= attention: sums 2 split-K partial planes of QKV + bias on load =====
// 16 query rows per block, 128 threads, grid 768.
__global__ void __launch_bounds__(128) attn_kernel(
    const float* __restrict__ part,     // 2 planes of [1024, 2304]
    const float* __restrict__ qkv_bias, // [2304]
    float* __restrict__ o)
{
    const int bh = blockIdx.x >> 1;
    const int half = blockIdx.x & 1;
    const int b = bh / Hv, h = bh % Hv;
    const int r0 = half * 16;

    __shared__ float q[16][68];
    __shared__ float kk[32][68];
    __shared__ float vv[32][68];
    __shared__ float a[16][33];

    const int tid = threadIdx.x;
    const size_t PS = (size_t)NT * 3 * Dv;  // plane stride
    const float* base0 = part + (size_t)(b * Mv) * (3 * Dv) + h * HDv;
    const float* base1 = base0 + PS;
    const float* bq = qkv_bias + h * HDv;

    #pragma unroll
    for (int rep = 0; rep < 8; rep++) {
        int idx = tid + rep * 128;
        int i = idx >> 6, d = idx & 63;
        size_t off = (size_t)(r0 + i) * (3 * Dv) + d;
        q[i][d] = base0[off] + base1[off] + bq[d];
    }
    #pragma unroll
    for (int rep = 0; rep < 16; rep++) {
        int idx = tid + rep * 128;
        int i = idx >> 6, d = idx & 63;
        size_t off = (size_t)i * (3 * Dv) + d;
        kk[i][d] = base0[off + Dv]     + base1[off + Dv]     + bq[Dv + d];
        vv[i][d] = base0[off + 2 * Dv] + base1[off + 2 * Dv] + bq[2 * Dv + d];
    }
    __syncthreads();

    #pragma unroll
    for (int rep = 0; rep < 4; rep++) {
        int idx = tid + rep * 128;
        int i = idx >> 5, j = idx & 31;
        float s = 0.f;
        #pragma unroll
        for (int d = 0; d < 64; d += 4) {
            float4 qa = *(const float4*)&q[i][d];
            float4 ka = *(const float4*)&kk[j][d];
            s += qa.x * ka.x + qa.y * ka.y + qa.z * ka.z + qa.w * ka.w;
        }
        a[i][j] = s * 0.125f;
    }
    __syncthreads();

    int warp = tid >> 5, lane = tid & 31;
    #pragma unroll
    for (int r = 0; r < 4; r++) {
        int i = warp * 4 + r;
        float v = a[i][lane];
        float mx = v;
        for (int off = 16; off; off >>= 1) mx = fmaxf(mx, __shfl_xor_sync(0xffffffffu, mx, off));
        float e = expf(v - mx);
        float sm = e;
        for (int off = 16; off; off >>= 1) sm += __shfl_xor_sync(0xffffffffu, sm, off);
        a[i][lane] = e / sm;
    }
    __syncthreads();

    float* obase = o + (size_t)(b * Mv + r0) * Dv + h * HDv;
    #pragma unroll
    for (int rep = 0; rep < 8; rep++) {
        int idx = tid + rep * 128;
        int i = idx >> 6, d = idx & 63;
        float s = 0.f;
        #pragma unroll
        for (int j = 0; j < 32; j++) s += a[i][j] * vv[j][d];
        obase[(size_t)i * Dv + d] = s;
    }
}

// ================ reduce split-K partials + bias (+relu), elementwise =======
__global__ void __launch_bounds__(256) reduce_bias_kernel(
    float* __restrict__ dst, const float* __restrict__ part, int nPart,
    const float* __restrict__ bias, int Ncols, int relu)
{
    const size_t total = (size_t)NT * Ncols;
    const size_t stride = (size_t)gridDim.x * blockDim.x;
    for (size_t idx = (size_t)blockIdx.x * blockDim.x + threadIdx.x;
         idx < total; idx += stride) {
        float s = 0.f;
        for (int p = 0; p < nPart; p++) s += part[(size_t)p * total + idx];
        if (bias) s += bias[idx % Ncols];
        if (relu) s = fmaxf(s, 0.f);
        dst[idx] = s;
    }
}

// ======== reduce split-K partials + bias + residual add + LayerNorm =========
__global__ void __launch_bounds__(256) reduce_addln_kernel(
    float* __restrict__ x, const float* __restrict__ part, int nPart,
    const float* __restrict__ bias,
    const float* __restrict__ w, const float* __restrict__ b)
{
    __shared__ float sh[8];
    __shared__ float s_mean, s_inv;
    const int row = blockIdx.x;
    float* xr = x + (size_t)row * Dv;
    const int tid = threadIdx.x, lane = tid & 31, warp = tid >> 5;
    const size_t planeStride = (size_t)NT * Dv;

    float v[3];
    float sum = 0.f;
    #pragma unroll
    for (int i = 0; i < 3; i++) {
        int idx = tid + 256 * i;
        float d = bias[idx];
        for (int p = 0; p < nPart; p++)
            d += part[(size_t)p * planeStride + (size_t)row * Dv + idx];
        v[i] = xr[idx] + d;
        sum += v[i];
    }
    for (int o = 16; o; o >>= 1) sum += __shfl_xor_sync(0xffffffffu, sum, o);
    if (lane == 0) sh[warp] = sum;
    __syncthreads();
    if (tid == 0) {
        float s = 0.f;
        for (int i = 0; i < 8; i++) s += sh[i];
        s_mean = s * (1.f / (float)Dv);
    }
    __syncthreads();
    float mean = s_mean;

    float sq = 0.f;
    #pragma unroll
    for (int i = 0; i < 3; i++) { float c = v[i] - mean; sq += c * c; }
    for (int o = 16; o; o >>= 1) sq += __shfl_xor_sync(0xffffffffu, sq, o);
    if (lane == 0) sh[warp] = sq;
    __syncthreads();
    if (tid == 0) {
        float s = 0.f;
        for (int i = 0; i < 8; i++) s += sh[i];
        s_inv = rsqrtf(s * (1.f / (float)Dv) + 1e-5f);
    }
    __syncthreads();
    float inv = s_inv;

    #pragma unroll
    for (int i = 0; i < 3; i++) {
        int idx = tid + 256 * i;
        xr[idx] = (v[i] - mean) * inv * w[idx] + b[idx];
    }
}

// ======================= launcher ===========================================
extern "C" void kernel_launch(void* const* d_in, const int* in_sizes, int n_in,
                              void* d_out, int out_size)
{
    const float* lhs       = (const float*)d_in[0];
    const float* attn_w    = (const float*)d_in[1];
    const float* attn_b    = (const float*)d_in[2];
    const float* in_proj_w = (const float*)d_in[3];
    const float* in_proj_b = (const float*)d_in[4];
    const float* out_w     = (const float*)d_in[5];
    const float* out_b     = (const float*)d_in[6];
    const float* ln1_w     = (const float*)d_in[7];
    const float* ln1_b     = (const float*)d_in[8];
    const float* lin1_w    = (const float*)d_in[9];
    const float* lin1_b    = (const float*)d_in[10];
    const float* lin2_w    = (const float*)d_in[11];
    const float* lin2_b    = (const float*)d_in[12];
    const float* ln2_w     = (const float*)d_in[13];
    const float* ln2_b     = (const float*)d_in[14];
    const float* cls_w1    = (const float*)d_in[15];
    const float* cls_w2    = (const float*)d_in[16];
    const float* cls_b2    = (const float*)d_in[17];
    const int*   pos       = (const int*)d_in[18];
    const int*   emask     = (const int*)d_in[19];
    float* out = (float*)d_out;

    float *x, *buf1, *hid, *part;
    cudaGetSymbolAddress((void**)&x,    g_x);
    cudaGetSymbolAddress((void**)&buf1, g_buf1);
    cudaGetSymbolAddress((void**)&hid,  g_hid);
    cudaGetSymbolAddress((void**)&part, g_part);

    cudaFuncSetAttribute(gemm_tc, cudaFuncAttributeMaxDynamicSharedMemorySize, GEMM_SMEM);

    pool_kernel<<<NT, 128>>>(lhs, attn_w, attn_b, pos, emask, x);

    for (int l = 0; l < Lv; l++) {
        // QKV: split-K 2 -> 288 blocks, partials consumed by attn (bias fused there)
        gemm_tc<<<dim3(18, 8, 2), 256, GEMM_SMEM>>>(
            x, in_proj_w + (size_t)l * 3 * Dv * Dv, nullptr, part, 3 * Dv, Dv, 384, 0);
        attn_kernel<<<Bv * Hv * 2, 128>>>(part, in_proj_b + (size_t)l * 3 * Dv, buf1);
        // out-proj: split-K 6 -> 288 blocks, reduce rides LN
        gemm_tc<<<dim3(6, 8, 6), 256, GEMM_SMEM>>>(
            buf1, out_w + (size_t)l * Dv * Dv, nullptr, part, Dv, Dv, 128, 0);
        reduce_addln_kernel<<<NT, 256>>>(x, part, 6, out_b + (size_t)l * Dv,
                                         ln1_w + (size_t)l * Dv, ln1_b + (size_t)l * Dv);
        // lin1: split-K 2 -> 384 blocks, bias+relu in small reduce pass
        gemm_tc<<<dim3(24, 8, 2), 256, GEMM_SMEM>>>(
            x, lin1_w + (size_t)l * DFFv * Dv, nullptr, part, DFFv, Dv, 384, 0);
        reduce_bias_kernel<<<1024, 256>>>(buf1, part, 2, lin1_b + (size_t)l * DFFv, DFFv, 1);
        // lin2: K=3072, split-K 6 -> 288 blocks, reduce rides LN
        gemm_tc<<<dim3(6, 8, 6), 256, GEMM_SMEM>>>(
            buf1, lin2_w + (size_t)l * Dv * DFFv, nullptr, part, Dv, DFFv, 512, 0);
        reduce_addln_kernel<<<NT, 256>>>(x, part, 6, lin2_b + (size_t)l * Dv,
                                         ln2_w + (size_t)l * Dv, ln2_b + (size_t)l * Dv);
    }

    // classifier stage 1: [1024,768]@[100,768]^T, split-K 4 -> 32 blocks
    gemm_tc<<<dim3(1, 8, 4), 256, GEMM_SMEM>>>(
        x, cls_w1, nullptr, part, 100, Dv, 192, 0);
    reduce_bias_kernel<<<1024, 256>>>(hid, part, 4, nullptr, 100, 0);
    // classifier stage 2: [1024,100]@[100000,100]^T -> 6256 blocks
    gemm_tc<<<dim3(782, 8, 1), 256, GEMM_SMEM>>>(
        hid, cls_w2, cls_b2, out, Ev, 100, 100, 0);
}

// round 9
// speedup vs baseline: 1.3144x; 1.0511x over previous
#include <cuda_runtime.h>
#include <math.h>
#include <stdint.h>

// Problem constants
#define Bv   32
#define Sv   512
#define Dv   768
#define Mv   32
#define Tv   30
#define Hv   12
#define HDv  64
#define DFFv 3072
#define Lv   4
#define Ev   100000
#define NT   1024           // B*M token rows

// ---------------- scratch (static device memory; no allocations) -------------
__device__ float g_x[NT * Dv];            // residual stream (exact fp32)
__device__ float g_xtf[NT * Dv];          // tf32-rounded copy of residual
__device__ float g_buf1[NT * DFFv];       // attn-out / FF hidden (tf32-rounded)
__device__ float g_hid[NT * 100];         // classifier hidden (tf32-rounded)
__device__ float g_part[2 * NT * DFFv];   // split-K partials

// ======================= helpers ============================================
__device__ __forceinline__ uint32_t f2tf32(float f) {
    uint32_t u;
    asm("cvt.rna.tf32.f32 %0, %1;" : "=r"(u) : "f"(f));
    return u;
}
__device__ __forceinline__ float rnd_tf32(float f) {
    return __uint_as_float(f2tf32(f));
}

__device__ __forceinline__ void mma_tf32(float* c, const uint32_t* a, const uint32_t* b) {
    asm volatile(
        "mma.sync.aligned.m16n8k8.row.col.f32.tf32.tf32.f32 "
        "{%0,%1,%2,%3}, {%4,%5,%6,%7}, {%8,%9}, {%0,%1,%2,%3};"
        : "+f"(c[0]), "+f"(c[1]), "+f"(c[2]), "+f"(c[3])
        : "r"(a[0]), "r"(a[1]), "r"(a[2]), "r"(a[3]),
          "r"(b[0]), "r"(b[1]));
}

__device__ __forceinline__ void cp16(unsigned dst, const float* src, int bytes) {
    asm volatile("cp.async.ca.shared.global [%0], [%1], 16, %2;\n"
                 :: "r"(dst), "l"(src), "r"(bytes));
}

// ======================= TF32 tensor-core GEMM ==============================
// C = A @ W^T (+bias,+relu,+round). A:[1024,K] tf32-rounded fp32 row-major,
// W:[N,K] raw fp32 row-major (cvt at consume). Tile 128x128x32, 256 thr,
// 8 warps (2x4), warp tile 64x32. Double-buffered cp.async.
// mode: bit0 = relu, bit1 = round output to tf32.
#define SMS 4608   // floats per tile stage: 128*36

__device__ __forceinline__ void fill_tiles(
    float* As, float* Ws, const float* __restrict__ A, const float* __restrict__ W,
    int rowBase, int colBase, int N, int K, int k0, int kEnd, int tid)
{
    #pragma unroll
    for (int i = 0; i < 4; i++) {
        int c = tid + i * 256;          // 0..1023
        int r = c >> 3, ck = c & 7;
        int gk = k0 + ck * 4;
        int ok = (gk < kEnd);
        const float* src = ok ? (A + (size_t)(rowBase + r) * K + gk) : A;
        unsigned d = (unsigned)__cvta_generic_to_shared(As + r * 36 + ck * 4);
        cp16(d, src, ok ? 16 : 0);
    }
    #pragma unroll
    for (int i = 0; i < 4; i++) {
        int c = tid + i * 256;
        int r = c >> 3, ck = c & 7;
        int gk = k0 + ck * 4;
        int n = colBase + r;
        int ok = (n < N) && (gk < kEnd);
        const float* src = ok ? (W + (size_t)n * K + gk) : W;
        unsigned d = (unsigned)__cvta_generic_to_shared(Ws + r * 36 + ck * 4);
        cp16(d, src, ok ? 16 : 0);
    }
}

__global__ void __launch_bounds__(256, 2) gemm_tc(
    const float* __restrict__ A, const float* __restrict__ W,
    const float* __restrict__ bias, float* __restrict__ C,
    int N, int K, int kChunk, int mode)
{
    extern __shared__ float smbuf[];
    float* AsBase = smbuf;              // [2][128][36]
    float* WsBase = smbuf + 2 * SMS;    // [2][128][36]

    const int tid = threadIdx.x;
    const int lane = tid & 31, wid = tid >> 5;
    const int wy = wid >> 2, wx = wid & 3;      // 2 x 4 warps
    const int lm = lane >> 2, lk = lane & 3;
    const int rowBase = blockIdx.y * 128;
    const int colBase = blockIdx.x * 128;
    const int kBase = blockIdx.z * kChunk;
    const int kEnd = min(K, kBase + kChunk);
    const int nT = (kEnd - kBase + 31) >> 5;

    float* Cp = C;
    if (gridDim.z > 1) Cp += (size_t)blockIdx.z * ((size_t)NT * N);

    float acc[4][4][4];
    #pragma unroll
    for (int i = 0; i < 4; i++)
        #pragma unroll
        for (int j = 0; j < 4; j++)
            #pragma unroll
            for (int q = 0; q < 4; q++) acc[i][j][q] = 0.f;

    fill_tiles(AsBase, WsBase, A, W, rowBase, colBase, N, K, kBase, kEnd, tid);
    asm volatile("cp.async.commit_group;\n" ::: "memory");

    for (int t = 0; t < nT; t++) {
        const int cur = t & 1;
        if (t + 1 < nT)
            fill_tiles(AsBase + (cur ^ 1) * SMS, WsBase + (cur ^ 1) * SMS,
                       A, W, rowBase, colBase, N, K, kBase + (t + 1) * 32, kEnd, tid);
        asm volatile("cp.async.commit_group;\n" ::: "memory");
        asm volatile("cp.async.wait_group 1;\n" ::: "memory");
        __syncthreads();

        const uint32_t* as = (const uint32_t*)(AsBase + cur * SMS);
        const float*    ws = WsBase + cur * SMS;
        #pragma unroll
        for (int k8 = 0; k8 < 4; k8++) {
            const int kb = k8 * 8;
            uint32_t af[4][4], bf[4][2];
            #pragma unroll
            for (int mt = 0; mt < 4; mt++) {
                int m = wy * 64 + mt * 16 + lm;
                af[mt][0] = as[m * 36 + kb + lk];          // pre-rounded: no cvt
                af[mt][1] = as[(m + 8) * 36 + kb + lk];
                af[mt][2] = as[m * 36 + kb + 4 + lk];
                af[mt][3] = as[(m + 8) * 36 + kb + 4 + lk];
            }
            #pragma unroll
            for (int nt = 0; nt < 4; nt++) {
                int n = wx * 32 + nt * 8 + lm;
                bf[nt][0] = f2tf32(ws[n * 36 + kb + lk]);
                bf[nt][1] = f2tf32(ws[n * 36 + kb + 4 + lk]);
            }
            #pragma unroll
            for (int mt = 0; mt < 4; mt++)
                #pragma unroll
                for (int nt = 0; nt < 4; nt++)
                    mma_tf32(acc[mt][nt], af[mt], bf[nt]);
        }
        __syncthreads();
    }

    // epilogue
    const int relu = mode & 1, rnd = mode & 2;
    #pragma unroll
    for (int mt = 0; mt < 4; mt++) {
        #pragma unroll
        for (int nt = 0; nt < 4; nt++) {
            int r0 = rowBase + wy * 64 + mt * 16 + lm;
            int c0 = colBase + wx * 32 + nt * 8 + lk * 2;
            float bx = 0.f, by = 0.f;
            if (bias) {
                if (c0 < N)     bx = bias[c0];
                if (c0 + 1 < N) by = bias[c0 + 1];
            }
            float v00 = acc[mt][nt][0] + bx, v01 = acc[mt][nt][1] + by;
            float v10 = acc[mt][nt][2] + bx, v11 = acc[mt][nt][3] + by;
            if (relu) {
                v00 = fmaxf(v00, 0.f); v01 = fmaxf(v01, 0.f);
                v10 = fmaxf(v10, 0.f); v11 = fmaxf(v11, 0.f);
            }
            if (rnd) {
                v00 = rnd_tf32(v00); v01 = rnd_tf32(v01);
                v10 = rnd_tf32(v10); v11 = rnd_tf32(v11);
            }
            if (c0 + 1 < N) {
                *(float2*)&Cp[(size_t)r0 * N + c0]       = make_float2(v00, v01);
                *(float2*)&Cp[(size_t)(r0 + 8) * N + c0] = make_float2(v10, v11);
            } else if (c0 < N) {
                Cp[(size_t)r0 * N + c0]       = v00;
                Cp[(size_t)(r0 + 8) * N + c0] = v10;
            }
        }
    }
}
#define GEMM_SMEM (4 * SMS * (int)sizeof(float))   // 73728 bytes

// ======================= mention pooling ====================================
__global__ void __launch_bounds__(128) pool_kernel(
    const float* __restrict__ lhs, const float* __restrict__ attn_w,
    const float* __restrict__ attn_b_p, const int* __restrict__ pos,
    const int* __restrict__ emask, float* __restrict__ x, float* __restrict__ xtf)
{
    int bm = blockIdx.x;
    int b = bm / Mv;
    __shared__ float logit[Tv];
    __shared__ float score[Tv];
    __shared__ int   validv[Tv];

    int tid = threadIdx.x, lane = tid & 31, warp = tid >> 5;

    if (tid == 0) {
        int ok = (emask[bm] != 0);
        int alive = 1;
        for (int t = 0; t < Tv; t++) {
            if (pos[bm * Tv + t] == -1) alive = 0;
            validv[t] = ok & alive;
        }
    }
    __syncthreads();

    float ab = attn_b_p[0];
    const float* lb = lhs + (size_t)b * Sv * Dv;

    for (int t = warp; t < Tv; t += 4) {
        float s = 0.f;
        for (int d = lane; d < Dv; d += 32) s += lb[t * Dv + d] * attn_w[d];
        for (int o = 16; o; o >>= 1) s += __shfl_xor_sync(0xffffffffu, s, o);
        if (lane == 0) logit[t] = (validv[t] ? s : 0.f) + ab;
    }
    __syncthreads();

    if (tid < 32) {
        float v = (tid < Tv) ? logit[tid] : -INFINITY;
        float mx = v;
        for (int o = 16; o; o >>= 1) mx = fmaxf(mx, __shfl_xor_sync(0xffffffffu, mx, o));
        float e = (tid < Tv) ? expf(v - mx) : 0.f;
        float sm = e;
        for (int o = 16; o; o >>= 1) sm += __shfl_xor_sync(0xffffffffu, sm, o);
        if (tid < Tv) score[tid] = e / sm;
    }
    __syncthreads();

    for (int d = tid; d < Dv; d += 128) {
        float s = 0.f;
        #pragma unroll
        for (int t = 0; t < Tv; t++)
            if (validv[t]) s += score[t] * lb[t * Dv + d];
        x[(size_t)bm * Dv + d]   = s;
        xtf[(size_t)bm * Dv + d] = rnd_tf32(s);
    }
}

// ======= attention: sums 2 split-K partial planes of QKV + bias on load =====
// 16 query rows per block, 128 threads, grid 768. Output tf32-rounded.
__global__ void __launch_bounds__(128) attn_kernel(
    const float* __restrict__ part,     // 2 planes of [1024, 2304]
    const float* __restrict__ qkv_bias, // [2304]
    float* __restrict__ o)
{
    const int bh = blockIdx.x >> 1;
    const int half = blockIdx.x & 1;
    const int b = bh / Hv, h = bh % Hv;
    const int r0 = half * 16;

    __shared__ float q[16][68];
    __shared__ float kk[32][68];
    __shared__ float vv[32][68];
    __shared__ float a[16][33];

    const int tid = threadIdx.x;
    const size_t PS = (size_t)NT * 3 * Dv;  // plane stride
    const float* base0 = part + (size_t)(b * Mv) * (3 * Dv) + h * HDv;
    const float* base1 = base0 + PS;
    const float* bq = qkv_bias + h * HDv;

    #pragma unroll
    for (int rep = 0; rep < 8; rep++) {
        int idx = tid + rep * 128;
        int i = idx >> 6, d = idx & 63;
        size_t off = (size_t)(r0 + i) * (3 * Dv) + d;
        q[i][d] = base0[off] + base1[off] + bq[d];
    }
    #pragma unroll
    for (int rep = 0; rep < 16; rep++) {
        int idx = tid + rep * 128;
        int i = idx >> 6, d = idx & 63;
        size_t off = (size_t)i * (3 * Dv) + d;
        kk[i][d] = base0[off + Dv]     + base1[off + Dv]     + bq[Dv + d];
        vv[i][d] = base0[off + 2 * Dv] + base1[off + 2 * Dv] + bq[2 * Dv + d];
    }
    __syncthreads();

    #pragma unroll
    for (int rep = 0; rep < 4; rep++) {
        int idx = tid + rep * 128;
        int i = idx >> 5, j = idx & 31;
        float s = 0.f;
        #pragma unroll
        for (int d = 0; d < 64; d += 4) {
            float4 qa = *(const float4*)&q[i][d];
            float4 ka = *(const float4*)&kk[j][d];
            s += qa.x * ka.x + qa.y * ka.y + qa.z * ka.z + qa.w * ka.w;
        }
        a[i][j] = s * 0.125f;
    }
    __syncthreads();

    int warp = tid >> 5, lane = tid & 31;
    #pragma unroll
    for (int r = 0; r < 4; r++) {
        int i = warp * 4 + r;
        float v = a[i][lane];
        float mx = v;
        for (int off = 16; off; off >>= 1) mx = fmaxf(mx, __shfl_xor_sync(0xffffffffu, mx, off));
        float e = expf(v - mx);
        float sm = e;
        for (int off = 16; off; off >>= 1) sm += __shfl_xor_sync(0xffffffffu, sm, off);
        a[i][lane] = e / sm;
    }
    __syncthreads();

    float* obase = o + (size_t)(b * Mv + r0) * Dv + h * HDv;
    #pragma unroll
    for (int rep = 0; rep < 8; rep++) {
        int idx = tid + rep * 128;
        int i = idx >> 6, d = idx & 63;
        float s = 0.f;
        #pragma unroll
        for (int j = 0; j < 32; j++) s += a[i][j] * vv[j][d];
        obase[(size_t)i * Dv + d] = rnd_tf32(s);
    }
}

// ================ reduce split-K partials + bias (+relu), round out =========
__global__ void __launch_bounds__(256) reduce_bias_kernel(
    float* __restrict__ dst, const float* __restrict__ part, int nPart,
    const float* __restrict__ bias, int Ncols, int relu)
{
    const size_t total = (size_t)NT * Ncols;
    const size_t stride = (size_t)gridDim.x * blockDim.x;
    for (size_t idx = (size_t)blockIdx.x * blockDim.x + threadIdx.x;
         idx < total; idx += stride) {
        float s = 0.f;
        for (int p = 0; p < nPart; p++) s += part[(size_t)p * total + idx];
        if (bias) s += bias[idx % Ncols];
        if (relu) s = fmaxf(s, 0.f);
        dst[idx] = rnd_tf32(s);
    }
}

// ===== reduce split-K partials + bias + residual add + LayerNorm ============
// Writes exact x (residual) and tf32-rounded xtf.
__global__ void __launch_bounds__(256) reduce_addln_kernel(
    float* __restrict__ x, float* __restrict__ xtf,
    const float* __restrict__ part, int nPart,
    const float* __restrict__ bias,
    const float* __restrict__ w, const float* __restrict__ b)
{
    __shared__ float sh[8];
    __shared__ float s_mean, s_inv;
    const int row = blockIdx.x;
    float* xr = x + (size_t)row * Dv;
    float* xt = xtf + (size_t)row * Dv;
    const int tid = threadIdx.x, lane = tid & 31, warp = tid >> 5;
    const size_t planeStride = (size_t)NT * Dv;

    float v[3];
    float sum = 0.f;
    #pragma unroll
    for (int i = 0; i < 3; i++) {
        int idx = tid + 256 * i;
        float d = bias[idx];
        for (int p = 0; p < nPart; p++)
            d += part[(size_t)p * planeStride + (size_t)row * Dv + idx];
        v[i] = xr[idx] + d;
        sum += v[i];
    }
    for (int o = 16; o; o >>= 1) sum += __shfl_xor_sync(0xffffffffu, sum, o);
    if (lane == 0) sh[warp] = sum;
    __syncthreads();
    if (tid == 0) {
        float s = 0.f;
        for (int i = 0; i < 8; i++) s += sh[i];
        s_mean = s * (1.f / (float)Dv);
    }
    __syncthreads();
    float mean = s_mean;

    float sq = 0.f;
    #pragma unroll
    for (int i = 0; i < 3; i++) { float c = v[i] - mean; sq += c * c; }
    for (int o = 16; o; o >>= 1) sq += __shfl_xor_sync(0xffffffffu, sq, o);
    if (lane == 0) sh[warp] = sq;
    __syncthreads();
    if (tid == 0) {
        float s = 0.f;
        for (int i = 0; i < 8; i++) s += sh[i];
        s_inv = rsqrtf(s * (1.f / (float)Dv) + 1e-5f);
    }
    __syncthreads();
    float inv = s_inv;

    #pragma unroll
    for (int i = 0; i < 3; i++) {
        int idx = tid + 256 * i;
        float o = (v[i] - mean) * inv * w[idx] + b[idx];
        xr[idx] = o;
        xt[idx] = rnd_tf32(o);
    }
}

// ======================= launcher ===========================================
extern "C" void kernel_launch(void* const* d_in, const int* in_sizes, int n_in,
                              void* d_out, int out_size)
{
    const float* lhs       = (const float*)d_in[0];
    const float* attn_w    = (const float*)d_in[1];
    const float* attn_b    = (const float*)d_in[2];
    const float* in_proj_w = (const float*)d_in[3];
    const float* in_proj_b = (const float*)d_in[4];
    const float* out_w     = (const float*)d_in[5];
    const float* out_b     = (const float*)d_in[6];
    const float* ln1_w     = (const float*)d_in[7];
    const float* ln1_b     = (const float*)d_in[8];
    const float* lin1_w    = (const float*)d_in[9];
    const float* lin1_b    = (const float*)d_in[10];
    const float* lin2_w    = (const float*)d_in[11];
    const float* lin2_b    = (const float*)d_in[12];
    const float* ln2_w     = (const float*)d_in[13];
    const float* ln2_b     = (const float*)d_in[14];
    const float* cls_w1    = (const float*)d_in[15];
    const float* cls_w2    = (const float*)d_in[16];
    const float* cls_b2    = (const float*)d_in[17];
    const int*   pos       = (const int*)d_in[18];
    const int*   emask     = (const int*)d_in[19];
    float* out = (float*)d_out;

    float *x, *xtf, *buf1, *hid, *part;
    cudaGetSymbolAddress((void**)&x,    g_x);
    cudaGetSymbolAddress((void**)&xtf,  g_xtf);
    cudaGetSymbolAddress((void**)&buf1, g_buf1);
    cudaGetSymbolAddress((void**)&hid,  g_hid);
    cudaGetSymbolAddress((void**)&part, g_part);

    cudaFuncSetAttribute(gemm_tc, cudaFuncAttributeMaxDynamicSharedMemorySize, GEMM_SMEM);

    pool_kernel<<<NT, 128>>>(lhs, attn_w, attn_b, pos, emask, x, xtf);

    for (int l = 0; l < Lv; l++) {
        // QKV: split-K 2 -> 288 blocks, partials consumed by attn (bias fused there)
        gemm_tc<<<dim3(18, 8, 2), 256, GEMM_SMEM>>>(
            xtf, in_proj_w + (size_t)l * 3 * Dv * Dv, nullptr, part, 3 * Dv, Dv, 384, 0);
        attn_kernel<<<Bv * Hv * 2, 128>>>(part, in_proj_b + (size_t)l * 3 * Dv, buf1);
        // out-proj: split-K 6 -> 288 blocks, reduce rides LN
        gemm_tc<<<dim3(6, 8, 6), 256, GEMM_SMEM>>>(
            buf1, out_w + (size_t)l * Dv * Dv, nullptr, part, Dv, Dv, 128, 0);
        reduce_addln_kernel<<<NT, 256>>>(x, xtf, part, 6, out_b + (size_t)l * Dv,
                                         ln1_w + (size_t)l * Dv, ln1_b + (size_t)l * Dv);
        // lin1: no split, bias+relu+round fused -> 192 blocks
        gemm_tc<<<dim3(24, 8, 1), 256, GEMM_SMEM>>>(
            xtf, lin1_w + (size_t)l * DFFv * Dv, lin1_b + (size_t)l * DFFv,
            buf1, DFFv, Dv, Dv, 3);
        // lin2: K=3072, split-K 6 -> 288 blocks, reduce rides LN
        gemm_tc<<<dim3(6, 8, 6), 256, GEMM_SMEM>>>(
            buf1, lin2_w + (size_t)l * Dv * DFFv, nullptr, part, Dv, DFFv, 512, 0);
        reduce_addln_kernel<<<NT, 256>>>(x, xtf, part, 6, lin2_b + (size_t)l * Dv,
                                         ln2_w + (size_t)l * Dv, ln2_b + (size_t)l * Dv);
    }

    // classifier stage 1: [1024,768]@[100,768]^T, split-K 4 -> 32 blocks
    gemm_tc<<<dim3(1, 8, 4), 256, GEMM_SMEM>>>(
        xtf, cls_w1, nullptr, part, 100, Dv, 192, 0);
    reduce_bias_kernel<<<1024, 256>>>(hid, part, 4, nullptr, 100, 0);
    // classifier stage 2: [1024,100]@[100000,100]^T -> 6256 blocks
    gemm_tc<<<dim3(782, 8, 1), 256, GEMM_SMEM>>>(
        hid, cls_w2, cls_b2, out, Ev, 100, 100, 0);
}